// round 1
// baseline (speedup 1.0000x reference)
#include <cuda_runtime.h>
#include <math.h>

#define B_SZ  2
#define S_CTX 2048
#define NH    16
#define DH    64
#define DM    1024
#define BQ    64
#define BK    64
#define PAD   68   // 68 % 4 == 0 -> float4-aligned rows, non-pow2 to break bank conflicts

// 16 MB scratch for z in [b, q, (h d)] layout -> projection is a plain GEMM.
__device__ float g_z[(size_t)B_SZ * S_CTX * DM];

// ---------------------------------------------------------------------------
// Flash attention: one block per (q-tile, head, batch). 64x64 tiles, 256 thr,
// each thread owns a 4x4 microtile of S and of O.
// ---------------------------------------------------------------------------
__global__ __launch_bounds__(256)
void attn_kernel(const float* __restrict__ qp,
                 const float* __restrict__ kp,
                 const float* __restrict__ vp) {
    extern __shared__ float sm[];
    float* Qs  = sm;                 // [BQ][PAD]  (row, d)
    float* Ks  = Qs + BQ * PAD;      // [BK][PAD]  (kcol, d)
    float* Vs  = Ks + BK * PAD;      // [BK][PAD]  (krow, d)
    float* Ss  = Vs + BK * PAD;      // [BQ][PAD]  (row, kcol)
    float* m_s = Ss + BQ * PAD;      // [BQ]
    float* l_s = m_s + BQ;           // [BQ]
    float* sc_s = l_s + BQ;          // [BQ]

    const int qt = blockIdx.x;
    const int h  = blockIdx.y;
    const int b  = blockIdx.z;
    const int tid = threadIdx.x;
    const int ty = tid >> 4;         // 0..15
    const int tx = tid & 15;         // 0..15
    const int r0 = ty * 4;
    const int c0 = tx * 4;

    const float* qb = qp + ((size_t)(b * S_CTX + qt * BQ)) * DM + h * DH;
    const float* kb = kp + ((size_t)(b * S_CTX)) * DM + h * DH;
    const float* vb = vp + ((size_t)(b * S_CTX)) * DM + h * DH;

    // load Q tile (64 rows x 64 floats) as float4
    for (int i = tid; i < BQ * 16; i += 256) {
        int row = i >> 4;
        int seg = (i & 15) << 2;
        *(float4*)&Qs[row * PAD + seg] =
            *(const float4*)(qb + (size_t)row * DM + seg);
    }
    if (tid < BQ) { m_s[tid] = -INFINITY; l_s[tid] = 0.f; }

    float o[4][4];
#pragma unroll
    for (int i = 0; i < 4; i++)
#pragma unroll
        for (int j = 0; j < 4; j++) o[i][j] = 0.f;

    const float inv_scale = 0.125f;  // 1/sqrt(64)

    for (int kt = 0; kt <= qt; ++kt) {
        __syncthreads();  // prev iteration done with Ks/Vs/Ss
        // load K,V tiles
        for (int i = tid; i < BK * 16; i += 256) {
            int row = i >> 4;
            int seg = (i & 15) << 2;
            size_t goff = (size_t)(kt * BK + row) * DM + seg;
            *(float4*)&Ks[row * PAD + seg] = *(const float4*)(kb + goff);
            *(float4*)&Vs[row * PAD + seg] = *(const float4*)(vb + goff);
        }
        __syncthreads();

        // S = Q K^T  (4x4 microtile per thread)
        float sreg[4][4];
#pragma unroll
        for (int i = 0; i < 4; i++)
#pragma unroll
            for (int j = 0; j < 4; j++) sreg[i][j] = 0.f;

#pragma unroll
        for (int kk = 0; kk < DH; kk += 4) {
            float4 qv[4], kv[4];
#pragma unroll
            for (int i = 0; i < 4; i++)
                qv[i] = *(float4*)&Qs[(r0 + i) * PAD + kk];
#pragma unroll
            for (int j = 0; j < 4; j++)
                kv[j] = *(float4*)&Ks[(c0 + j) * PAD + kk];
#pragma unroll
            for (int i = 0; i < 4; i++)
#pragma unroll
                for (int j = 0; j < 4; j++)
                    sreg[i][j] += qv[i].x * kv[j].x + qv[i].y * kv[j].y +
                                  qv[i].z * kv[j].z + qv[i].w * kv[j].w;
        }

        // scale + causal mask (only the diagonal tile needs masking)
        const bool diag = (kt == qt);
#pragma unroll
        for (int i = 0; i < 4; i++)
#pragma unroll
            for (int j = 0; j < 4; j++) {
                float sv = sreg[i][j] * inv_scale;
                if (diag && (c0 + j > r0 + i)) sv = -INFINITY;
                sreg[i][j] = sv;
            }
        // write S to smem for row reductions
#pragma unroll
        for (int i = 0; i < 4; i++) {
            float4 w = make_float4(sreg[i][0], sreg[i][1], sreg[i][2], sreg[i][3]);
            *(float4*)&Ss[(r0 + i) * PAD + c0] = w;
        }
        __syncthreads();

        // row max + rescale factor (64 threads)
        if (tid < BQ) {
            float mo = m_s[tid];
            float mx = mo;
            const float* row = &Ss[tid * PAD];
#pragma unroll 8
            for (int c = 0; c < BK; c++) mx = fmaxf(mx, row[c]);
            float sc = __expf(mo - mx);     // mo = -inf on first tile -> 0
            m_s[tid] = mx;
            sc_s[tid] = sc;
        }
        __syncthreads();

        // exp in parallel on register copies; rescale O
#pragma unroll
        for (int i = 0; i < 4; i++) {
            float mrow = m_s[r0 + i];
            float scr  = sc_s[r0 + i];
            float4 p;
            p.x = __expf(sreg[i][0] - mrow);
            p.y = __expf(sreg[i][1] - mrow);
            p.z = __expf(sreg[i][2] - mrow);
            p.w = __expf(sreg[i][3] - mrow);
            *(float4*)&Ss[(r0 + i) * PAD + c0] = p;
#pragma unroll
            for (int j = 0; j < 4; j++) o[i][j] *= scr;
        }
        __syncthreads();

        // l update (reads Ss; PV below also only reads Ss — no race)
        if (tid < BQ) {
            float s = 0.f;
            const float* row = &Ss[tid * PAD];
#pragma unroll 8
            for (int c = 0; c < BK; c++) s += row[c];
            l_s[tid] = l_s[tid] * sc_s[tid] + s;
        }

        // O += P @ V  (thread owns rows r0..r0+3, d-cols c0..c0+3)
#pragma unroll
        for (int kc = 0; kc < BK; kc += 4) {
            float4 pv[4], vv[4];
#pragma unroll
            for (int i = 0; i < 4; i++)
                pv[i] = *(float4*)&Ss[(r0 + i) * PAD + kc];
#pragma unroll
            for (int t = 0; t < 4; t++)
                vv[t] = *(float4*)&Vs[(kc + t) * PAD + c0];
#pragma unroll
            for (int i = 0; i < 4; i++) {
                o[i][0] += pv[i].x * vv[0].x; o[i][1] += pv[i].x * vv[0].y;
                o[i][2] += pv[i].x * vv[0].z; o[i][3] += pv[i].x * vv[0].w;
                o[i][0] += pv[i].y * vv[1].x; o[i][1] += pv[i].y * vv[1].y;
                o[i][2] += pv[i].y * vv[1].z; o[i][3] += pv[i].y * vv[1].w;
                o[i][0] += pv[i].z * vv[2].x; o[i][1] += pv[i].z * vv[2].y;
                o[i][2] += pv[i].z * vv[2].z; o[i][3] += pv[i].z * vv[2].w;
                o[i][0] += pv[i].w * vv[3].x; o[i][1] += pv[i].w * vv[3].y;
                o[i][2] += pv[i].w * vv[3].z; o[i][3] += pv[i].w * vv[3].w;
            }
        }
    }
    __syncthreads();

    // normalize and write z to scratch in [b, q, h*64+d] layout
#pragma unroll
    for (int i = 0; i < 4; i++) {
        float linv = 1.f / l_s[r0 + i];
        float4 w = make_float4(o[i][0] * linv, o[i][1] * linv,
                               o[i][2] * linv, o[i][3] * linv);
        size_t off = (size_t)(b * S_CTX + qt * BQ + r0 + i) * DM + h * DH + c0;
        *(float4*)&g_z[off] = w;
    }
}

// ---------------------------------------------------------------------------
// Projection GEMM: out[M=4096][N=1024] = Z @ W + b.  64x64x16 tiles.
// W_O (H, D, M) row-major == W[(h*64+d)][m] row-major 1024x1024.
// ---------------------------------------------------------------------------
#define GBK 16
#define GPAD 68

__global__ __launch_bounds__(256)
void proj_kernel(const float* __restrict__ W,
                 const float* __restrict__ bias,
                 float* __restrict__ out) {
    __shared__ float As[GBK][GPAD];   // [k][m]
    __shared__ float Bs[GBK][GPAD];   // [k][n]

    const int tid = threadIdx.x;
    const int ty = tid >> 4, tx = tid & 15;
    const int bm = blockIdx.y * 64;
    const int bn = blockIdx.x * 64;

    float acc[4][4];
#pragma unroll
    for (int i = 0; i < 4; i++)
#pragma unroll
        for (int j = 0; j < 4; j++) acc[i][j] = 0.f;

    const int a_row = tid >> 2, a_seg = (tid & 3) << 2;   // A: 64x16
    const int b_row = tid >> 4, b_col = (tid & 15) << 2;  // B: 16x64

    for (int k0 = 0; k0 < DM; k0 += GBK) {
        __syncthreads();
        {   // A tile, stored transposed As[k][m]
            float4 a = *(const float4*)(g_z + (size_t)(bm + a_row) * DM + k0 + a_seg);
            As[a_seg + 0][a_row] = a.x;
            As[a_seg + 1][a_row] = a.y;
            As[a_seg + 2][a_row] = a.z;
            As[a_seg + 3][a_row] = a.w;
        }
        {   // B tile direct
            *(float4*)&Bs[b_row][b_col] =
                *(const float4*)(W + (size_t)(k0 + b_row) * DM + bn + b_col);
        }
        __syncthreads();

#pragma unroll
        for (int kk = 0; kk < GBK; kk++) {
            float4 av = *(float4*)&As[kk][ty * 4];
            float4 bv = *(float4*)&Bs[kk][tx * 4];
            acc[0][0] += av.x * bv.x; acc[0][1] += av.x * bv.y;
            acc[0][2] += av.x * bv.z; acc[0][3] += av.x * bv.w;
            acc[1][0] += av.y * bv.x; acc[1][1] += av.y * bv.y;
            acc[1][2] += av.y * bv.z; acc[1][3] += av.y * bv.w;
            acc[2][0] += av.z * bv.x; acc[2][1] += av.z * bv.y;
            acc[2][2] += av.z * bv.z; acc[2][3] += av.z * bv.w;
            acc[3][0] += av.w * bv.x; acc[3][1] += av.w * bv.y;
            acc[3][2] += av.w * bv.z; acc[3][3] += av.w * bv.w;
        }
    }

    float4 bv = *(const float4*)(bias + bn + tx * 4);
#pragma unroll
    for (int i = 0; i < 4; i++) {
        float4 w = make_float4(acc[i][0] + bv.x, acc[i][1] + bv.y,
                               acc[i][2] + bv.z, acc[i][3] + bv.w);
        *(float4*)&out[(size_t)(bm + ty * 4 + i) * DM + bn + tx * 4] = w;
    }
}

// ---------------------------------------------------------------------------
extern "C" void kernel_launch(void* const* d_in, const int* in_sizes, int n_in,
                              void* d_out, int out_size) {
    const float* q    = (const float*)d_in[0];
    const float* k    = (const float*)d_in[1];
    const float* v    = (const float*)d_in[2];
    const float* res  = (const float*)d_in[3];
    const float* W_O  = (const float*)d_in[4];
    const float* b_O  = (const float*)d_in[5];
    float* out = (float*)d_out;

    const size_t half = (size_t)B_SZ * S_CTX * DM;  // 4,194,304 elements

    const int smem_bytes = (4 * BQ * PAD + 3 * BQ) * (int)sizeof(float); // 70400
    cudaFuncSetAttribute(attn_kernel,
                         cudaFuncAttributeMaxDynamicSharedMemorySize, smem_bytes);

    attn_kernel<<<dim3(S_CTX / BQ, NH, B_SZ), 256, smem_bytes>>>(q, k, v);
    proj_kernel<<<dim3(DM / 64, (B_SZ * S_CTX) / 64), 256>>>(W_O, b_O, out);

    // residual passthrough = second half of output tuple
    cudaMemcpyAsync(out + half, res, half * sizeof(float),
                    cudaMemcpyDeviceToDevice);
}

// round 2
// speedup vs baseline: 3.2883x; 3.2883x over previous
#include <cuda_runtime.h>
#include <math.h>

#define B_SZ  2
#define S_CTX 2048
#define NH    16
#define DH    64
#define DM    1024
#define BQ    64
#define BK    64

#define KPAD 68   // bank(4g+c) distinct for B-frag gather of K
#define VPAD 72   // bank(8c+g) distinct for B-frag gather of V
#define SPAD 68   // bank(4g+c) distinct for A-frag gather of P

// 16 MB scratch for z in [b, q, (h d)] layout -> projection is a plain GEMM.
__device__ float g_z[(size_t)B_SZ * S_CTX * DM];

// ---------------------------------------------------------------------------
// helpers
// ---------------------------------------------------------------------------
__device__ __forceinline__ unsigned tf32u(float x) {
    unsigned u;
    asm("cvt.rna.tf32.f32 %0, %1;" : "=r"(u) : "f"(x));
    return u;
}
__device__ __forceinline__ float tf32f(float x) {
    return __uint_as_float(tf32u(x));
}

__device__ __forceinline__ void mma_tf32(float c[4], const unsigned a[4],
                                         unsigned b0, unsigned b1) {
    asm volatile(
        "mma.sync.aligned.m16n8k8.row.col.f32.tf32.tf32.f32 "
        "{%0,%1,%2,%3}, {%4,%5,%6,%7}, {%8,%9}, {%0,%1,%2,%3};\n"
        : "+f"(c[0]), "+f"(c[1]), "+f"(c[2]), "+f"(c[3])
        : "r"(a[0]), "r"(a[1]), "r"(a[2]), "r"(a[3]), "r"(b0), "r"(b1));
}

// ---------------------------------------------------------------------------
// Flash attention, tf32 tensor cores. Block = 256 thr = 8 warps (4x2 grid),
// warp computes a 16x32 fragment of the 64x64 tile.
// ---------------------------------------------------------------------------
__global__ __launch_bounds__(256)
void attn_kernel(const float* __restrict__ qp,
                 const float* __restrict__ kp,
                 const float* __restrict__ vp) {
    extern __shared__ float sm[];
    float* Ks  = sm;                  // [BK][KPAD]  (kpos, d)
    float* Vs  = Ks + BK * KPAD;      // [BK][VPAD]  (kpos, d)
    float* SP  = Vs + BK * VPAD;      // [BQ][SPAD]  Q at init, then S / P
    float* red = SP + BQ * SPAD;      // [256] partial max / sum
    float* m_s = red + 256;           // [BQ]
    float* l_s = m_s + BQ;            // [BQ]
    float* sc_s = l_s + BQ;           // [BQ]

    const int qt = blockIdx.x;
    const int h  = blockIdx.y;
    const int b  = blockIdx.z;
    const int tid  = threadIdx.x;
    const int wid  = tid >> 5;
    const int lane = tid & 31;
    const int g = lane >> 2;          // 0..7
    const int c = lane & 3;           // 0..3
    const int wy = wid >> 1;          // 0..3
    const int wx = wid & 1;           // 0..1
    const int m0 = wy * 16;
    const int n0 = wx * 32;

    const float* qb = qp + ((size_t)(b * S_CTX + qt * BQ)) * DM + h * DH;
    const float* kb = kp + ((size_t)(b * S_CTX)) * DM + h * DH;
    const float* vb = vp + ((size_t)(b * S_CTX)) * DM + h * DH;

    // load Q into SP (tf32-rounded)
    for (int i = tid; i < BQ * 16; i += 256) {
        int row = i >> 4;
        int seg = (i & 15) << 2;
        float4 v4 = *(const float4*)(qb + (size_t)row * DM + seg);
        v4.x = tf32f(v4.x); v4.y = tf32f(v4.y);
        v4.z = tf32f(v4.z); v4.w = tf32f(v4.w);
        *(float4*)&SP[row * SPAD + seg] = v4;
    }
    if (tid < BQ) { m_s[tid] = -INFINITY; l_s[tid] = 0.f; }
    __syncthreads();

    // Q fragments in registers, reused for every kt
    unsigned qa[8][4];
#pragma unroll
    for (int kk = 0; kk < 8; kk++) {
        qa[kk][0] = __float_as_uint(SP[(m0 + g)     * SPAD + kk * 8 + c]);
        qa[kk][1] = __float_as_uint(SP[(m0 + g + 8) * SPAD + kk * 8 + c]);
        qa[kk][2] = __float_as_uint(SP[(m0 + g)     * SPAD + kk * 8 + c + 4]);
        qa[kk][3] = __float_as_uint(SP[(m0 + g + 8) * SPAD + kk * 8 + c + 4]);
    }

    float of[4][4];
#pragma unroll
    for (int nt = 0; nt < 4; nt++)
#pragma unroll
        for (int j = 0; j < 4; j++) of[nt][j] = 0.f;

    for (int kt = 0; kt <= qt; ++kt) {
        __syncthreads();   // prior iter done with Ks/Vs/SP (covers Q-frag reads on iter 0)
        // load K,V tiles (tf32-rounded)
        for (int i = tid; i < BK * 16; i += 256) {
            int row = i >> 4;
            int seg = (i & 15) << 2;
            size_t goff = (size_t)(kt * BK + row) * DM + seg;
            float4 kv = *(const float4*)(kb + goff);
            float4 vv = *(const float4*)(vb + goff);
            kv.x = tf32f(kv.x); kv.y = tf32f(kv.y);
            kv.z = tf32f(kv.z); kv.w = tf32f(kv.w);
            vv.x = tf32f(vv.x); vv.y = tf32f(vv.y);
            vv.z = tf32f(vv.z); vv.w = tf32f(vv.w);
            *(float4*)&Ks[row * KPAD + seg] = kv;
            *(float4*)&Vs[row * VPAD + seg] = vv;
        }
        __syncthreads();

        // S = Q K^T : per warp 16x32, 8 k-steps x 4 n-tiles
        float sf[4][4];
#pragma unroll
        for (int nt = 0; nt < 4; nt++)
#pragma unroll
            for (int j = 0; j < 4; j++) sf[nt][j] = 0.f;

#pragma unroll
        for (int kk = 0; kk < 8; kk++) {
#pragma unroll
            for (int nt = 0; nt < 4; nt++) {
                int n = n0 + nt * 8 + g;
                unsigned b0 = __float_as_uint(Ks[n * KPAD + kk * 8 + c]);
                unsigned b1 = __float_as_uint(Ks[n * KPAD + kk * 8 + c + 4]);
                mma_tf32(sf[nt], qa[kk], b0, b1);
            }
        }

        // scale + causal mask + write S to SP (float2 per c-pair)
        const bool diag = (kt == qt);
        const int rowA = m0 + g, rowB = m0 + g + 8;
#pragma unroll
        for (int nt = 0; nt < 4; nt++) {
            int col = n0 + nt * 8 + 2 * c;
            float s0 = sf[nt][0] * 0.125f, s1 = sf[nt][1] * 0.125f;
            float s2 = sf[nt][2] * 0.125f, s3 = sf[nt][3] * 0.125f;
            if (diag) {
                if (col     > rowA) s0 = -INFINITY;
                if (col + 1 > rowA) s1 = -INFINITY;
                if (col     > rowB) s2 = -INFINITY;
                if (col + 1 > rowB) s3 = -INFINITY;
            }
            *(float2*)&SP[rowA * SPAD + col] = make_float2(s0, s1);
            *(float2*)&SP[rowB * SPAD + col] = make_float2(s2, s3);
        }
        __syncthreads();

        // partial row max: thread handles row=tid>>2, quarter=tid&3 (16 cols)
        {
            int row = tid >> 2;
            int base = (tid & 3) * 16;
            float mx = -INFINITY;
#pragma unroll
            for (int j = 0; j < 4; j++) {
                float4 x = *(float4*)&SP[row * SPAD + base + j * 4];
                mx = fmaxf(mx, fmaxf(fmaxf(x.x, x.y), fmaxf(x.z, x.w)));
            }
            red[tid] = mx;
        }
        __syncthreads();
        if (tid < BQ) {
            float mo = m_s[tid];
            float mn = fmaxf(fmaxf(red[tid * 4], red[tid * 4 + 1]),
                             fmaxf(red[tid * 4 + 2], red[tid * 4 + 3]));
            mn = fmaxf(mo, mn);
            sc_s[tid] = __expf(mo - mn);   // 0 on first tile
            m_s[tid] = mn;
        }
        __syncthreads();

        // exp pass (tf32-rounded P) + partial row sum; rescale O
        {
            int row = tid >> 2;
            int base = (tid & 3) * 16;
            float mrow = m_s[row];
            float sum = 0.f;
#pragma unroll
            for (int j = 0; j < 4; j++) {
                float4 x = *(float4*)&SP[row * SPAD + base + j * 4];
                x.x = __expf(x.x - mrow); x.y = __expf(x.y - mrow);
                x.z = __expf(x.z - mrow); x.w = __expf(x.w - mrow);
                sum += x.x + x.y + x.z + x.w;
                x.x = tf32f(x.x); x.y = tf32f(x.y);
                x.z = tf32f(x.z); x.w = tf32f(x.w);
                *(float4*)&SP[row * SPAD + base + j * 4] = x;
            }
            red[tid] = sum;
        }
        {
            float scA = sc_s[m0 + g];
            float scB = sc_s[m0 + g + 8];
#pragma unroll
            for (int nt = 0; nt < 4; nt++) {
                of[nt][0] *= scA; of[nt][1] *= scA;
                of[nt][2] *= scB; of[nt][3] *= scB;
            }
        }
        __syncthreads();

        // l update (64 threads) runs alongside PV (reads only red/sc_s/l_s)
        if (tid < BQ) {
            l_s[tid] = l_s[tid] * sc_s[tid] +
                       (red[tid * 4] + red[tid * 4 + 1] +
                        red[tid * 4 + 2] + red[tid * 4 + 3]);
        }

        // O += P @ V
#pragma unroll
        for (int kk = 0; kk < 8; kk++) {
            unsigned pa[4];
            pa[0] = __float_as_uint(SP[(m0 + g)     * SPAD + kk * 8 + c]);
            pa[1] = __float_as_uint(SP[(m0 + g + 8) * SPAD + kk * 8 + c]);
            pa[2] = __float_as_uint(SP[(m0 + g)     * SPAD + kk * 8 + c + 4]);
            pa[3] = __float_as_uint(SP[(m0 + g + 8) * SPAD + kk * 8 + c + 4]);
#pragma unroll
            for (int nt = 0; nt < 4; nt++) {
                int n = n0 + nt * 8 + g;
                unsigned b0 = __float_as_uint(Vs[(kk * 8 + c)     * VPAD + n]);
                unsigned b1 = __float_as_uint(Vs[(kk * 8 + c + 4) * VPAD + n]);
                mma_tf32(of[nt], pa, b0, b1);
            }
        }
    }
    __syncthreads();   // l_s final

    // normalize + write z in [b, q, h*64+d]
    {
        float liA = 1.f / l_s[m0 + g];
        float liB = 1.f / l_s[m0 + g + 8];
        size_t baseA = (size_t)(b * S_CTX + qt * BQ + m0 + g)     * DM + h * DH;
        size_t baseB = (size_t)(b * S_CTX + qt * BQ + m0 + g + 8) * DM + h * DH;
#pragma unroll
        for (int nt = 0; nt < 4; nt++) {
            int col = n0 + nt * 8 + 2 * c;
            *(float2*)&g_z[baseA + col] = make_float2(of[nt][0] * liA, of[nt][1] * liA);
            *(float2*)&g_z[baseB + col] = make_float2(of[nt][2] * liB, of[nt][3] * liB);
        }
    }
}

// ---------------------------------------------------------------------------
// Projection GEMM (tf32 mma): out[4096][1024] = Z @ W + b. 64x64 tiles, KC=64.
// ---------------------------------------------------------------------------
#define GAPAD 68
#define GBPAD 72

__global__ __launch_bounds__(256)
void proj_kernel(const float* __restrict__ W,
                 const float* __restrict__ bias,
                 float* __restrict__ out) {
    __shared__ float As[64 * GAPAD];   // [m][k]
    __shared__ float Bs[64 * GBPAD];   // [k][n]

    const int tid  = threadIdx.x;
    const int wid  = tid >> 5;
    const int lane = tid & 31;
    const int g = lane >> 2;
    const int c = lane & 3;
    const int wy = wid >> 1, wx = wid & 1;
    const int m0 = wy * 16, n0 = wx * 32;
    const int bm = blockIdx.y * 64;
    const int bn = blockIdx.x * 64;

    float acc[4][4];
#pragma unroll
    for (int nt = 0; nt < 4; nt++)
#pragma unroll
        for (int j = 0; j < 4; j++) acc[nt][j] = 0.f;

    for (int k0 = 0; k0 < DM; k0 += 64) {
        __syncthreads();
        for (int i = tid; i < 64 * 16; i += 256) {
            int row = i >> 4;
            int seg = (i & 15) << 2;
            float4 a = *(const float4*)(g_z + (size_t)(bm + row) * DM + k0 + seg);
            a.x = tf32f(a.x); a.y = tf32f(a.y);
            a.z = tf32f(a.z); a.w = tf32f(a.w);
            *(float4*)&As[row * GAPAD + seg] = a;
            float4 w = *(const float4*)(W + (size_t)(k0 + row) * DM + bn + seg);
            w.x = tf32f(w.x); w.y = tf32f(w.y);
            w.z = tf32f(w.z); w.w = tf32f(w.w);
            *(float4*)&Bs[row * GBPAD + seg] = w;
        }
        __syncthreads();

#pragma unroll
        for (int kk = 0; kk < 8; kk++) {
            unsigned ua[4];
            ua[0] = __float_as_uint(As[(m0 + g)     * GAPAD + kk * 8 + c]);
            ua[1] = __float_as_uint(As[(m0 + g + 8) * GAPAD + kk * 8 + c]);
            ua[2] = __float_as_uint(As[(m0 + g)     * GAPAD + kk * 8 + c + 4]);
            ua[3] = __float_as_uint(As[(m0 + g + 8) * GAPAD + kk * 8 + c + 4]);
#pragma unroll
            for (int nt = 0; nt < 4; nt++) {
                int n = n0 + nt * 8 + g;
                unsigned b0 = __float_as_uint(Bs[(kk * 8 + c)     * GBPAD + n]);
                unsigned b1 = __float_as_uint(Bs[(kk * 8 + c + 4) * GBPAD + n]);
                mma_tf32(acc[nt], ua, b0, b1);
            }
        }
    }

#pragma unroll
    for (int nt = 0; nt < 4; nt++) {
        int col = bn + n0 + nt * 8 + 2 * c;
        float b0 = bias[col], b1 = bias[col + 1];
        *(float2*)&out[(size_t)(bm + m0 + g)     * DM + col] =
            make_float2(acc[nt][0] + b0, acc[nt][1] + b1);
        *(float2*)&out[(size_t)(bm + m0 + g + 8) * DM + col] =
            make_float2(acc[nt][2] + b0, acc[nt][3] + b1);
    }
}

// ---------------------------------------------------------------------------
extern "C" void kernel_launch(void* const* d_in, const int* in_sizes, int n_in,
                              void* d_out, int out_size) {
    const float* q    = (const float*)d_in[0];
    const float* k    = (const float*)d_in[1];
    const float* v    = (const float*)d_in[2];
    const float* res  = (const float*)d_in[3];
    const float* W_O  = (const float*)d_in[4];
    const float* b_O  = (const float*)d_in[5];
    float* out = (float*)d_out;

    const size_t half = (size_t)B_SZ * S_CTX * DM;

    const int smem_bytes =
        (BK * KPAD + BK * VPAD + BQ * SPAD + 256 + 3 * BQ) * (int)sizeof(float);
    cudaFuncSetAttribute(attn_kernel,
                         cudaFuncAttributeMaxDynamicSharedMemorySize, smem_bytes);

    attn_kernel<<<dim3(S_CTX / BQ, NH, B_SZ), 256, smem_bytes>>>(q, k, v);
    proj_kernel<<<dim3(DM / 64, (B_SZ * S_CTX) / 64), 256>>>(W_O, b_O, out);

    cudaMemcpyAsync(out + half, res, half * sizeof(float),
                    cudaMemcpyDeviceToDevice);
}

// round 3
// speedup vs baseline: 4.3018x; 1.3082x over previous
#include <cuda_runtime.h>
#include <math.h>

#define B_SZ  2
#define S_CTX 2048
#define NH    16
#define DH    64
#define DM    1024
#define BQ    128
#define BK    64

#define KPAD 68   // bank = 4g+c  (conflict-free K b-frag gather)
#define VPAD 72   // bank = 8c+g  (conflict-free V b-frag gather)
#define QPAD 68

// scratch: z in [b, q, (h d)] (tf32-rounded), W pre-rounded to tf32
__device__ float g_z[(size_t)B_SZ * S_CTX * DM];
__device__ float g_w[DM * DM];

// ---------------------------------------------------------------------------
__device__ __forceinline__ unsigned tf32u(float x) {
    unsigned u;
    asm("cvt.rna.tf32.f32 %0, %1;" : "=r"(u) : "f"(x));
    return u;
}
__device__ __forceinline__ float tf32f(float x) { return __uint_as_float(tf32u(x)); }

__device__ __forceinline__ void mma_tf32(float c[4], const unsigned a[4],
                                         unsigned b0, unsigned b1) {
    asm volatile(
        "mma.sync.aligned.m16n8k8.row.col.f32.tf32.tf32.f32 "
        "{%0,%1,%2,%3}, {%4,%5,%6,%7}, {%8,%9}, {%0,%1,%2,%3};\n"
        : "+f"(c[0]), "+f"(c[1]), "+f"(c[2]), "+f"(c[3])
        : "r"(a[0]), "r"(a[1]), "r"(a[2]), "r"(a[3]), "r"(b0), "r"(b1));
}

__device__ __forceinline__ void cp16(void* dst_smem, const void* src) {
    unsigned d = (unsigned)__cvta_generic_to_shared(dst_smem);
    asm volatile("cp.async.ca.shared.global [%0], [%1], 16;\n"
                 :: "r"(d), "l"(src) : "memory");
}
#define CP_COMMIT() asm volatile("cp.async.commit_group;\n" ::: "memory")
#define CP_WAIT1()  asm volatile("cp.async.wait_group 1;\n" ::: "memory")
#define CP_WAIT0()  asm volatile("cp.async.wait_group 0;\n" ::: "memory")

// ---------------------------------------------------------------------------
// Flash attention: 8 warps, warp w owns rows 16w..16w+15 of a 128-row q tile.
// Softmax fully register-resident; P->A-frag via shuffles. K/V double-buffered.
// ---------------------------------------------------------------------------
__device__ __forceinline__ void attn_issue(float* dst, const float* kb,
                                           const float* vb, int kt, int tid) {
    float* Ks = dst;
    float* Vs = dst + BK * KPAD;
    for (int i = tid; i < BK * 16; i += 256) {
        int row = i >> 4, seg = (i & 15) << 2;
        size_t goff = (size_t)(kt * BK + row) * DM + seg;
        cp16(&Ks[row * KPAD + seg], kb + goff);
        cp16(&Vs[row * VPAD + seg], vb + goff);
    }
    CP_COMMIT();
}

__global__ __launch_bounds__(256, 2)
void attn_kernel(const float* __restrict__ qp,
                 const float* __restrict__ kp,
                 const float* __restrict__ vp) {
    extern __shared__ float sm[];
    const int BUFSZ = BK * KPAD + BK * VPAD;   // 8960 floats per buffer

    const int qt = blockIdx.x, h = blockIdx.y, b = blockIdx.z;
    const int tid = threadIdx.x, w = tid >> 5, lane = tid & 31;
    const int g = lane >> 2, c = lane & 3;
    const int m0 = w * 16;

    const float* qb = qp + ((size_t)(b * S_CTX + qt * BQ)) * DM + h * DH;
    const float* kb = kp + ((size_t)b * S_CTX) * DM + h * DH;
    const float* vb = vp + ((size_t)b * S_CTX) * DM + h * DH;

    // ---- stage Q, build register fragments (tf32) ----
    for (int i = tid; i < BQ * 16; i += 256) {
        int row = i >> 4, seg = (i & 15) << 2;
        *(float4*)&sm[row * QPAD + seg] = *(const float4*)(qb + (size_t)row * DM + seg);
    }
    __syncthreads();
    unsigned qa[8][4];
#pragma unroll
    for (int kk = 0; kk < 8; kk++) {
        qa[kk][0] = tf32u(sm[(m0 + g)     * QPAD + kk * 8 + c]);
        qa[kk][1] = tf32u(sm[(m0 + g + 8) * QPAD + kk * 8 + c]);
        qa[kk][2] = tf32u(sm[(m0 + g)     * QPAD + kk * 8 + c + 4]);
        qa[kk][3] = tf32u(sm[(m0 + g + 8) * QPAD + kk * 8 + c + 4]);
    }
    __syncthreads();

    const int ktmax = 2 * qt + 1;
    attn_issue(sm, kb, vb, 0, tid);

    float of[8][4];
#pragma unroll
    for (int nt = 0; nt < 8; nt++)
#pragma unroll
        for (int j = 0; j < 4; j++) of[nt][j] = 0.f;

    float mA = -INFINITY, mB = -INFINITY, lA = 0.f, lB = 0.f;
    const int rowA = qt * BQ + m0 + g;      // global q row
    const int rowB = rowA + 8;
    const int wrow_max = qt * BQ + m0 + 15;
    const int l0 = (lane & ~3) | (c >> 1);  // shuffle src lanes for P transpose
    const int l1 = l0 + 2;

    for (int kt = 0; kt <= ktmax; kt++) {
        if (kt < ktmax) { attn_issue(sm + ((kt + 1) & 1) * BUFSZ, kb, vb, kt + 1, tid); CP_WAIT1(); }
        else           { CP_WAIT0(); }
        __syncthreads();

        float* Ks = sm + (kt & 1) * BUFSZ;
        float* Vs = Ks + BK * KPAD;

        // in-place tf32 rounding of the freshly landed K/V tiles
        for (int i2 = tid; i2 < 2048; i2 += 256) {
            int i = i2 & 1023;
            int row = i >> 4, seg = (i & 15) << 2;
            float* p = (i2 < 1024) ? &Ks[row * KPAD + seg] : &Vs[row * VPAD + seg];
            float4 x = *(float4*)p;
            x.x = tf32f(x.x); x.y = tf32f(x.y);
            x.z = tf32f(x.z); x.w = tf32f(x.w);
            *(float4*)p = x;
        }
        __syncthreads();

        if (kt * 64 <= wrow_max) {   // warp-uniform: tile not fully masked
            // ---- S = Q K^T ----
            float sf[8][4];
#pragma unroll
            for (int nt = 0; nt < 8; nt++)
#pragma unroll
                for (int j = 0; j < 4; j++) sf[nt][j] = 0.f;
#pragma unroll
            for (int kk = 0; kk < 8; kk++)
#pragma unroll
                for (int nt = 0; nt < 8; nt++) {
                    const float* kr = &Ks[(nt * 8 + g) * KPAD + kk * 8 + c];
                    mma_tf32(sf[nt], qa[kk], __float_as_uint(kr[0]),
                             __float_as_uint(kr[4]));
                }

            // ---- scale + causal mask ----
            const bool msk = (kt >= 2 * qt);
#pragma unroll
            for (int nt = 0; nt < 8; nt++) {
                sf[nt][0] *= 0.125f; sf[nt][1] *= 0.125f;
                sf[nt][2] *= 0.125f; sf[nt][3] *= 0.125f;
                if (msk) {
                    int col = kt * 64 + nt * 8 + 2 * c;
                    if (col     > rowA) sf[nt][0] = -INFINITY;
                    if (col + 1 > rowA) sf[nt][1] = -INFINITY;
                    if (col     > rowB) sf[nt][2] = -INFINITY;
                    if (col + 1 > rowB) sf[nt][3] = -INFINITY;
                }
            }

            // ---- row max (regs + 2 shuffles) ----
            float mxA = -INFINITY, mxB = -INFINITY;
#pragma unroll
            for (int nt = 0; nt < 8; nt++) {
                mxA = fmaxf(mxA, fmaxf(sf[nt][0], sf[nt][1]));
                mxB = fmaxf(mxB, fmaxf(sf[nt][2], sf[nt][3]));
            }
            mxA = fmaxf(mxA, __shfl_xor_sync(0xffffffff, mxA, 1));
            mxA = fmaxf(mxA, __shfl_xor_sync(0xffffffff, mxA, 2));
            mxB = fmaxf(mxB, __shfl_xor_sync(0xffffffff, mxB, 1));
            mxB = fmaxf(mxB, __shfl_xor_sync(0xffffffff, mxB, 2));

            float mAn = fmaxf(mA, mxA), mBn = fmaxf(mB, mxB);
            float scA = __expf(mA - mAn), scB = __expf(mB - mBn);
            mA = mAn; mB = mBn;

            // ---- exp + row sum; P tf32-rounded in regs ----
            float sA = 0.f, sB = 0.f;
#pragma unroll
            for (int nt = 0; nt < 8; nt++) {
                float p0 = __expf(sf[nt][0] - mA);
                float p1 = __expf(sf[nt][1] - mA);
                float p2 = __expf(sf[nt][2] - mB);
                float p3 = __expf(sf[nt][3] - mB);
                sA += p0 + p1; sB += p2 + p3;
                sf[nt][0] = tf32f(p0); sf[nt][1] = tf32f(p1);
                sf[nt][2] = tf32f(p2); sf[nt][3] = tf32f(p3);
            }
            sA += __shfl_xor_sync(0xffffffff, sA, 1);
            sA += __shfl_xor_sync(0xffffffff, sA, 2);
            sB += __shfl_xor_sync(0xffffffff, sB, 1);
            sB += __shfl_xor_sync(0xffffffff, sB, 2);
            lA = lA * scA + sA;
            lB = lB * scB + sB;
#pragma unroll
            for (int nt = 0; nt < 8; nt++) {
                of[nt][0] *= scA; of[nt][1] *= scA;
                of[nt][2] *= scB; of[nt][3] *= scB;
            }

            // ---- O += P @ V  (P C-frag -> A-frag via shuffles) ----
#pragma unroll
            for (int kb2 = 0; kb2 < 8; kb2++) {
                float x0 = __shfl_sync(0xffffffff, sf[kb2][0], l0);
                float x1 = __shfl_sync(0xffffffff, sf[kb2][1], l0);
                float x2 = __shfl_sync(0xffffffff, sf[kb2][2], l0);
                float x3 = __shfl_sync(0xffffffff, sf[kb2][3], l0);
                float y0 = __shfl_sync(0xffffffff, sf[kb2][0], l1);
                float y1 = __shfl_sync(0xffffffff, sf[kb2][1], l1);
                float y2 = __shfl_sync(0xffffffff, sf[kb2][2], l1);
                float y3 = __shfl_sync(0xffffffff, sf[kb2][3], l1);
                unsigned pa[4];
                pa[0] = __float_as_uint((c & 1) ? x1 : x0);
                pa[1] = __float_as_uint((c & 1) ? x3 : x2);
                pa[2] = __float_as_uint((c & 1) ? y1 : y0);
                pa[3] = __float_as_uint((c & 1) ? y3 : y2);
#pragma unroll
                for (int nt = 0; nt < 8; nt++) {
                    const float* v0 = &Vs[(kb2 * 8 + c) * VPAD + nt * 8 + g];
                    mma_tf32(of[nt], pa, __float_as_uint(v0[0]),
                             __float_as_uint(v0[4 * VPAD]));
                }
            }
        }
        __syncthreads();
    }

    // ---- epilogue: normalize, tf32-round, store z ----
    float liA = 1.f / lA, liB = 1.f / lB;
    size_t baseA = ((size_t)b * S_CTX + rowA) * DM + h * DH;
    size_t baseB = baseA + (size_t)8 * DM;
#pragma unroll
    for (int nt = 0; nt < 8; nt++) {
        int col = nt * 8 + 2 * c;
        *(float2*)&g_z[baseA + col] =
            make_float2(tf32f(of[nt][0] * liA), tf32f(of[nt][1] * liA));
        *(float2*)&g_z[baseB + col] =
            make_float2(tf32f(of[nt][2] * liB), tf32f(of[nt][3] * liB));
    }
}

// ---------------------------------------------------------------------------
// W pre-round to tf32 (one float4 per thread)
// ---------------------------------------------------------------------------
__global__ void convw_kernel(const float* __restrict__ W) {
    int i = (blockIdx.x * 256 + threadIdx.x) * 4;
    float4 x = *(const float4*)(W + i);
    x.x = tf32f(x.x); x.y = tf32f(x.y);
    x.z = tf32f(x.z); x.w = tf32f(x.w);
    *(float4*)(g_w + i) = x;
}

// ---------------------------------------------------------------------------
// Projection: out[4096][1024] = Z @ Wtf32 + b. 128x128 tile, k-chunk 32,
// double-buffered cp.async; warp tile 32x64 (2 m-frags x 8 n-frags).
// ---------------------------------------------------------------------------
#define APAD 36
#define BPAD 136

__device__ __forceinline__ void proj_issue(float* dst, int bm, int bn,
                                           int k0, int tid) {
    float* As = dst;
    float* Bs = dst + 128 * APAD;
#pragma unroll
    for (int it = 0; it < 4; it++) {
        int i = tid + it * 256;
        int ar = i >> 3, as = (i & 7) << 2;
        cp16(&As[ar * APAD + as], g_z + (size_t)(bm + ar) * DM + k0 + as);
        int br = i >> 5, bs = (i & 31) << 2;
        cp16(&Bs[br * BPAD + bs], g_w + (size_t)(k0 + br) * DM + bn + bs);
    }
    CP_COMMIT();
}

__global__ __launch_bounds__(256, 2)
void proj_kernel(const float* __restrict__ bias, float* __restrict__ out) {
    extern __shared__ float sm[];
    const int BUFSZ = 128 * APAD + 32 * BPAD;   // 8960 floats

    const int tid = threadIdx.x, w = tid >> 5, lane = tid & 31;
    const int g = lane >> 2, c = lane & 3;
    const int wy = w >> 1, wx = w & 1;
    const int m0 = wy * 32, n0 = wx * 64;
    const int bm = blockIdx.y * 128, bn = blockIdx.x * 128;

    float acc[2][8][4];
#pragma unroll
    for (int mf = 0; mf < 2; mf++)
#pragma unroll
        for (int nt = 0; nt < 8; nt++)
#pragma unroll
            for (int j = 0; j < 4; j++) acc[mf][nt][j] = 0.f;

    proj_issue(sm, bm, bn, 0, tid);

    for (int ch = 0; ch < 32; ch++) {
        if (ch < 31) { proj_issue(sm + ((ch + 1) & 1) * BUFSZ, bm, bn, (ch + 1) * 32, tid); CP_WAIT1(); }
        else        { CP_WAIT0(); }
        __syncthreads();

        float* As = sm + (ch & 1) * BUFSZ;
        float* Bs = As + 128 * APAD;
#pragma unroll
        for (int kk = 0; kk < 4; kk++) {
            unsigned ua[2][4];
#pragma unroll
            for (int mf = 0; mf < 2; mf++) {
                int row = m0 + 16 * mf;
                ua[mf][0] = __float_as_uint(As[(row + g)     * APAD + kk * 8 + c]);
                ua[mf][1] = __float_as_uint(As[(row + g + 8) * APAD + kk * 8 + c]);
                ua[mf][2] = __float_as_uint(As[(row + g)     * APAD + kk * 8 + c + 4]);
                ua[mf][3] = __float_as_uint(As[(row + g + 8) * APAD + kk * 8 + c + 4]);
            }
#pragma unroll
            for (int nt = 0; nt < 8; nt++) {
                const float* bp = &Bs[(kk * 8 + c) * BPAD + n0 + nt * 8 + g];
                unsigned b0 = __float_as_uint(bp[0]);
                unsigned b1 = __float_as_uint(bp[4 * BPAD]);
                mma_tf32(acc[0][nt], ua[0], b0, b1);
                mma_tf32(acc[1][nt], ua[1], b0, b1);
            }
        }
        __syncthreads();
    }

#pragma unroll
    for (int mf = 0; mf < 2; mf++)
#pragma unroll
        for (int nt = 0; nt < 8; nt++) {
            int col = bn + n0 + nt * 8 + 2 * c;
            float b0 = bias[col], b1 = bias[col + 1];
            int row = bm + m0 + 16 * mf + g;
            *(float2*)&out[(size_t)row * DM + col] =
                make_float2(acc[mf][nt][0] + b0, acc[mf][nt][1] + b1);
            *(float2*)&out[(size_t)(row + 8) * DM + col] =
                make_float2(acc[mf][nt][2] + b0, acc[mf][nt][3] + b1);
        }
}

// ---------------------------------------------------------------------------
extern "C" void kernel_launch(void* const* d_in, const int* in_sizes, int n_in,
                              void* d_out, int out_size) {
    const float* q   = (const float*)d_in[0];
    const float* k   = (const float*)d_in[1];
    const float* v   = (const float*)d_in[2];
    const float* res = (const float*)d_in[3];
    const float* W_O = (const float*)d_in[4];
    const float* b_O = (const float*)d_in[5];
    float* out = (float*)d_out;

    const size_t half = (size_t)B_SZ * S_CTX * DM;

    const int attn_smem = 2 * (BK * KPAD + BK * VPAD) * (int)sizeof(float); // 71680
    const int proj_smem = 2 * (128 * APAD + 32 * BPAD) * (int)sizeof(float); // 71680
    cudaFuncSetAttribute(attn_kernel,
                         cudaFuncAttributeMaxDynamicSharedMemorySize, attn_smem);
    cudaFuncSetAttribute(proj_kernel,
                         cudaFuncAttributeMaxDynamicSharedMemorySize, proj_smem);

    cudaMemcpyAsync(out + half, res, half * sizeof(float),
                    cudaMemcpyDeviceToDevice);
    convw_kernel<<<DM * DM / 1024, 256>>>(W_O);
    attn_kernel<<<dim3(S_CTX / BQ, NH, B_SZ), 256, attn_smem>>>(q, k, v);
    proj_kernel<<<dim3(DM / 128, (B_SZ * S_CTX) / 128), 256, proj_smem>>>(b_O, out);
}

// round 4
// speedup vs baseline: 5.7056x; 1.3263x over previous
#include <cuda_runtime.h>
#include <math.h>

#define B_SZ  2
#define S_CTX 2048
#define NH    16
#define DH    64
#define DM    1024
#define BQ    128
#define BK    64
#define NQT   (S_CTX / BQ)   // 16

#define KPAD 68   // bank = 4g+c  (conflict-free K b-frag gather)
#define VPAD 72   // bank = 8c+g  (conflict-free V b-frag gather)
#define QPAD 68

// scratch: z (tf32-rounded), and tf32 pre-rounded W / K / V
__device__ float g_z[(size_t)B_SZ * S_CTX * DM];
__device__ float g_w[DM * DM];
__device__ float g_k[(size_t)B_SZ * S_CTX * DM];
__device__ float g_v[(size_t)B_SZ * S_CTX * DM];

// ---------------------------------------------------------------------------
__device__ __forceinline__ unsigned tf32u(float x) {
    unsigned u;
    asm("cvt.rna.tf32.f32 %0, %1;" : "=r"(u) : "f"(x));
    return u;
}
__device__ __forceinline__ float tf32f(float x) { return __uint_as_float(tf32u(x)); }

__device__ __forceinline__ void mma_tf32(float c[4], const unsigned a[4],
                                         unsigned b0, unsigned b1) {
    asm volatile(
        "mma.sync.aligned.m16n8k8.row.col.f32.tf32.tf32.f32 "
        "{%0,%1,%2,%3}, {%4,%5,%6,%7}, {%8,%9}, {%0,%1,%2,%3};\n"
        : "+f"(c[0]), "+f"(c[1]), "+f"(c[2]), "+f"(c[3])
        : "r"(a[0]), "r"(a[1]), "r"(a[2]), "r"(a[3]), "r"(b0), "r"(b1));
}

__device__ __forceinline__ void cp16(void* dst_smem, const void* src) {
    unsigned d = (unsigned)__cvta_generic_to_shared(dst_smem);
    asm volatile("cp.async.ca.shared.global [%0], [%1], 16;\n"
                 :: "r"(d), "l"(src) : "memory");
}
#define CP_COMMIT() asm volatile("cp.async.commit_group;\n" ::: "memory")
#define CP_WAIT1()  asm volatile("cp.async.wait_group 1;\n" ::: "memory")
#define CP_WAIT0()  asm volatile("cp.async.wait_group 0;\n" ::: "memory")

// ---------------------------------------------------------------------------
// prep: tf32-round W, K, V into scratch (one float4 per thread)
// ---------------------------------------------------------------------------
#define W_F4  (DM * DM / 4)                       // 262144
#define KV_F4 ((size_t)B_SZ * S_CTX * DM / 4)     // 1048576
#define PREP_F4 (W_F4 + 2 * 1048576)              // 2359296

__global__ void prep_kernel(const float* __restrict__ W,
                            const float* __restrict__ K,
                            const float* __restrict__ V) {
    int i = blockIdx.x * 256 + threadIdx.x;
    const float4* src;
    float4* dst;
    if (i < W_F4)                 { src = (const float4*)W + i;            dst = (float4*)g_w + i; }
    else if (i < W_F4 + 1048576)  { int j = i - W_F4;                      src = (const float4*)K + j; dst = (float4*)g_k + j; }
    else                          { int j = i - (W_F4 + 1048576);          src = (const float4*)V + j; dst = (float4*)g_v + j; }
    float4 x = *src;
    x.x = tf32f(x.x); x.y = tf32f(x.y);
    x.z = tf32f(x.z); x.w = tf32f(x.w);
    *dst = x;
}

// ---------------------------------------------------------------------------
// Flash attention: 8 warps, warp w owns rows 16w..16w+15 of a 128-row q tile.
// K/V pre-rounded; double-buffered cp.async; LPT 1D grid (big qt first).
// ---------------------------------------------------------------------------
__device__ __forceinline__ void attn_issue(float* dst, const float* kb,
                                           const float* vb, int kt, int tid) {
    float* Ks = dst;
    float* Vs = dst + BK * KPAD;
    for (int i = tid; i < BK * 16; i += 256) {
        int row = i >> 4, seg = (i & 15) << 2;
        size_t goff = (size_t)(kt * BK + row) * DM + seg;
        cp16(&Ks[row * KPAD + seg], kb + goff);
        cp16(&Vs[row * VPAD + seg], vb + goff);
    }
    CP_COMMIT();
}

__global__ __launch_bounds__(256, 2)
void attn_kernel(const float* __restrict__ qp) {
    extern __shared__ float sm[];
    const int BUFSZ = BK * KPAD + BK * VPAD;   // 8960 floats per buffer

    // LPT: largest qt first. 512 blocks: [qt-rank 0..15][hb 0..31]
    const int qt = NQT - 1 - (blockIdx.x >> 5);
    const int hb = blockIdx.x & 31;
    const int h = hb & 15;
    const int b = hb >> 4;

    const int tid = threadIdx.x, w = tid >> 5, lane = tid & 31;
    const int g = lane >> 2, c = lane & 3;
    const int m0 = w * 16;

    const float* qb = qp  + ((size_t)(b * S_CTX + qt * BQ)) * DM + h * DH;
    const float* kb = g_k + ((size_t)b * S_CTX) * DM + h * DH;
    const float* vb = g_v + ((size_t)b * S_CTX) * DM + h * DH;

    // ---- stage Q, build register fragments (tf32) ----
    for (int i = tid; i < BQ * 16; i += 256) {
        int row = i >> 4, seg = (i & 15) << 2;
        *(float4*)&sm[row * QPAD + seg] = *(const float4*)(qb + (size_t)row * DM + seg);
    }
    __syncthreads();
    unsigned qa[8][4];
#pragma unroll
    for (int kk = 0; kk < 8; kk++) {
        qa[kk][0] = tf32u(sm[(m0 + g)     * QPAD + kk * 8 + c]);
        qa[kk][1] = tf32u(sm[(m0 + g + 8) * QPAD + kk * 8 + c]);
        qa[kk][2] = tf32u(sm[(m0 + g)     * QPAD + kk * 8 + c + 4]);
        qa[kk][3] = tf32u(sm[(m0 + g + 8) * QPAD + kk * 8 + c + 4]);
    }
    __syncthreads();

    const int ktmax = 2 * qt + 1;
    attn_issue(sm, kb, vb, 0, tid);

    float of[8][4];
#pragma unroll
    for (int nt = 0; nt < 8; nt++)
#pragma unroll
        for (int j = 0; j < 4; j++) of[nt][j] = 0.f;

    float mA = -INFINITY, mB = -INFINITY, lA = 0.f, lB = 0.f;
    const int rowA = qt * BQ + m0 + g;      // global q row
    const int rowB = rowA + 8;
    const int wrow_max = qt * BQ + m0 + 15;
    const int l0 = (lane & ~3) | (c >> 1);  // shuffle src lanes for P transpose
    const int l1 = l0 + 2;

    for (int kt = 0; kt <= ktmax; kt++) {
        if (kt < ktmax) { attn_issue(sm + ((kt + 1) & 1) * BUFSZ, kb, vb, kt + 1, tid); CP_WAIT1(); }
        else           { CP_WAIT0(); }
        __syncthreads();   // cp.async data visible to all warps

        float* Ks = sm + (kt & 1) * BUFSZ;
        float* Vs = Ks + BK * KPAD;

        if (kt * 64 <= wrow_max) {   // warp-uniform: tile not fully masked
            // ---- S = Q K^T ----
            float sf[8][4];
#pragma unroll
            for (int nt = 0; nt < 8; nt++)
#pragma unroll
                for (int j = 0; j < 4; j++) sf[nt][j] = 0.f;
#pragma unroll
            for (int kk = 0; kk < 8; kk++)
#pragma unroll
                for (int nt = 0; nt < 8; nt++) {
                    const float* kr = &Ks[(nt * 8 + g) * KPAD + kk * 8 + c];
                    mma_tf32(sf[nt], qa[kk], __float_as_uint(kr[0]),
                             __float_as_uint(kr[4]));
                }

            // ---- scale + causal mask ----
            const bool msk = (kt >= 2 * qt);
#pragma unroll
            for (int nt = 0; nt < 8; nt++) {
                sf[nt][0] *= 0.125f; sf[nt][1] *= 0.125f;
                sf[nt][2] *= 0.125f; sf[nt][3] *= 0.125f;
                if (msk) {
                    int col = kt * 64 + nt * 8 + 2 * c;
                    if (col     > rowA) sf[nt][0] = -INFINITY;
                    if (col + 1 > rowA) sf[nt][1] = -INFINITY;
                    if (col     > rowB) sf[nt][2] = -INFINITY;
                    if (col + 1 > rowB) sf[nt][3] = -INFINITY;
                }
            }

            // ---- row max (regs + 2 shuffles) ----
            float mxA = -INFINITY, mxB = -INFINITY;
#pragma unroll
            for (int nt = 0; nt < 8; nt++) {
                mxA = fmaxf(mxA, fmaxf(sf[nt][0], sf[nt][1]));
                mxB = fmaxf(mxB, fmaxf(sf[nt][2], sf[nt][3]));
            }
            mxA = fmaxf(mxA, __shfl_xor_sync(0xffffffff, mxA, 1));
            mxA = fmaxf(mxA, __shfl_xor_sync(0xffffffff, mxA, 2));
            mxB = fmaxf(mxB, __shfl_xor_sync(0xffffffff, mxB, 1));
            mxB = fmaxf(mxB, __shfl_xor_sync(0xffffffff, mxB, 2));

            float mAn = fmaxf(mA, mxA), mBn = fmaxf(mB, mxB);
            float scA = __expf(mA - mAn), scB = __expf(mB - mBn);
            mA = mAn; mB = mBn;

            // ---- exp + row sum; P tf32-rounded in regs ----
            float sA = 0.f, sB = 0.f;
#pragma unroll
            for (int nt = 0; nt < 8; nt++) {
                float p0 = __expf(sf[nt][0] - mA);
                float p1 = __expf(sf[nt][1] - mA);
                float p2 = __expf(sf[nt][2] - mB);
                float p3 = __expf(sf[nt][3] - mB);
                sA += p0 + p1; sB += p2 + p3;
                sf[nt][0] = tf32f(p0); sf[nt][1] = tf32f(p1);
                sf[nt][2] = tf32f(p2); sf[nt][3] = tf32f(p3);
            }
            sA += __shfl_xor_sync(0xffffffff, sA, 1);
            sA += __shfl_xor_sync(0xffffffff, sA, 2);
            sB += __shfl_xor_sync(0xffffffff, sB, 1);
            sB += __shfl_xor_sync(0xffffffff, sB, 2);
            lA = lA * scA + sA;
            lB = lB * scB + sB;
#pragma unroll
            for (int nt = 0; nt < 8; nt++) {
                of[nt][0] *= scA; of[nt][1] *= scA;
                of[nt][2] *= scB; of[nt][3] *= scB;
            }

            // ---- O += P @ V  (P C-frag -> A-frag via shuffles) ----
#pragma unroll
            for (int kb2 = 0; kb2 < 8; kb2++) {
                float x0 = __shfl_sync(0xffffffff, sf[kb2][0], l0);
                float x1 = __shfl_sync(0xffffffff, sf[kb2][1], l0);
                float x2 = __shfl_sync(0xffffffff, sf[kb2][2], l0);
                float x3 = __shfl_sync(0xffffffff, sf[kb2][3], l0);
                float y0 = __shfl_sync(0xffffffff, sf[kb2][0], l1);
                float y1 = __shfl_sync(0xffffffff, sf[kb2][1], l1);
                float y2 = __shfl_sync(0xffffffff, sf[kb2][2], l1);
                float y3 = __shfl_sync(0xffffffff, sf[kb2][3], l1);
                unsigned pa[4];
                pa[0] = __float_as_uint((c & 1) ? x1 : x0);
                pa[1] = __float_as_uint((c & 1) ? x3 : x2);
                pa[2] = __float_as_uint((c & 1) ? y1 : y0);
                pa[3] = __float_as_uint((c & 1) ? y3 : y2);
#pragma unroll
                for (int nt = 0; nt < 8; nt++) {
                    const float* v0 = &Vs[(kb2 * 8 + c) * VPAD + nt * 8 + g];
                    mma_tf32(of[nt], pa, __float_as_uint(v0[0]),
                             __float_as_uint(v0[4 * VPAD]));
                }
            }
        }
        __syncthreads();   // all warps done with buffer before re-issue
    }

    // ---- epilogue: normalize, tf32-round, store z ----
    float liA = 1.f / lA, liB = 1.f / lB;
    size_t baseA = ((size_t)b * S_CTX + rowA) * DM + h * DH;
    size_t baseB = baseA + (size_t)8 * DM;
#pragma unroll
    for (int nt = 0; nt < 8; nt++) {
        int col = nt * 8 + 2 * c;
        *(float2*)&g_z[baseA + col] =
            make_float2(tf32f(of[nt][0] * liA), tf32f(of[nt][1] * liA));
        *(float2*)&g_z[baseB + col] =
            make_float2(tf32f(of[nt][2] * liB), tf32f(of[nt][3] * liB));
    }
}

// ---------------------------------------------------------------------------
// Projection: out[4096][1024] = Z @ Wtf32 + b. 128x128 tile, k-chunk 32,
// 4 warps, warp tile 64x64 (4 m-frags x 8 n-frags) -> 1.0 LDS per MMA.
// ---------------------------------------------------------------------------
#define APAD 36
#define BPAD 136

__device__ __forceinline__ void proj_issue(float* dst, int bm, int bn,
                                           int k0, int tid) {
    float* As = dst;
    float* Bs = dst + 128 * APAD;
#pragma unroll
    for (int it = 0; it < 8; it++) {
        int i = tid + it * 128;
        int ar = i >> 3, as = (i & 7) << 2;
        cp16(&As[ar * APAD + as], g_z + (size_t)(bm + ar) * DM + k0 + as);
        int br = i >> 5, bs = (i & 31) << 2;
        cp16(&Bs[br * BPAD + bs], g_w + (size_t)(k0 + br) * DM + bn + bs);
    }
    CP_COMMIT();
}

__global__ __launch_bounds__(128, 2)
void proj_kernel(const float* __restrict__ bias, float* __restrict__ out) {
    extern __shared__ float sm[];
    const int BUFSZ = 128 * APAD + 32 * BPAD;   // 8960 floats

    const int tid = threadIdx.x, w = tid >> 5, lane = tid & 31;
    const int g = lane >> 2, c = lane & 3;
    const int wy = w >> 1, wx = w & 1;
    const int m0 = wy * 64, n0 = wx * 64;
    const int bm = blockIdx.y * 128, bn = blockIdx.x * 128;

    float acc[4][8][4];
#pragma unroll
    for (int mf = 0; mf < 4; mf++)
#pragma unroll
        for (int nt = 0; nt < 8; nt++)
#pragma unroll
            for (int j = 0; j < 4; j++) acc[mf][nt][j] = 0.f;

    proj_issue(sm, bm, bn, 0, tid);

    for (int ch = 0; ch < 32; ch++) {
        if (ch < 31) { proj_issue(sm + ((ch + 1) & 1) * BUFSZ, bm, bn, (ch + 1) * 32, tid); CP_WAIT1(); }
        else        { CP_WAIT0(); }
        __syncthreads();

        float* As = sm + (ch & 1) * BUFSZ;
        float* Bs = As + 128 * APAD;
#pragma unroll
        for (int kk = 0; kk < 4; kk++) {
            unsigned ua[4][4];
#pragma unroll
            for (int mf = 0; mf < 4; mf++) {
                int row = m0 + 16 * mf;
                ua[mf][0] = __float_as_uint(As[(row + g)     * APAD + kk * 8 + c]);
                ua[mf][1] = __float_as_uint(As[(row + g + 8) * APAD + kk * 8 + c]);
                ua[mf][2] = __float_as_uint(As[(row + g)     * APAD + kk * 8 + c + 4]);
                ua[mf][3] = __float_as_uint(As[(row + g + 8) * APAD + kk * 8 + c + 4]);
            }
#pragma unroll
            for (int nt = 0; nt < 8; nt++) {
                const float* bp = &Bs[(kk * 8 + c) * BPAD + n0 + nt * 8 + g];
                unsigned b0 = __float_as_uint(bp[0]);
                unsigned b1 = __float_as_uint(bp[4 * BPAD]);
#pragma unroll
                for (int mf = 0; mf < 4; mf++)
                    mma_tf32(acc[mf][nt], ua[mf], b0, b1);
            }
        }
        __syncthreads();
    }

#pragma unroll
    for (int mf = 0; mf < 4; mf++)
#pragma unroll
        for (int nt = 0; nt < 8; nt++) {
            int col = bn + n0 + nt * 8 + 2 * c;
            float b0 = bias[col], b1 = bias[col + 1];
            int row = bm + m0 + 16 * mf + g;
            *(float2*)&out[(size_t)row * DM + col] =
                make_float2(acc[mf][nt][0] + b0, acc[mf][nt][1] + b1);
            *(float2*)&out[(size_t)(row + 8) * DM + col] =
                make_float2(acc[mf][nt][2] + b0, acc[mf][nt][3] + b1);
        }
}

// ---------------------------------------------------------------------------
extern "C" void kernel_launch(void* const* d_in, const int* in_sizes, int n_in,
                              void* d_out, int out_size) {
    const float* q   = (const float*)d_in[0];
    const float* k   = (const float*)d_in[1];
    const float* v   = (const float*)d_in[2];
    const float* res = (const float*)d_in[3];
    const float* W_O = (const float*)d_in[4];
    const float* b_O = (const float*)d_in[5];
    float* out = (float*)d_out;

    const size_t half = (size_t)B_SZ * S_CTX * DM;

    const int attn_smem = 2 * (BK * KPAD + BK * VPAD) * (int)sizeof(float);  // 71680
    const int proj_smem = 2 * (128 * APAD + 32 * BPAD) * (int)sizeof(float); // 71680
    cudaFuncSetAttribute(attn_kernel,
                         cudaFuncAttributeMaxDynamicSharedMemorySize, attn_smem);
    cudaFuncSetAttribute(proj_kernel,
                         cudaFuncAttributeMaxDynamicSharedMemorySize, proj_smem);

    cudaMemcpyAsync(out + half, res, half * sizeof(float),
                    cudaMemcpyDeviceToDevice);
    prep_kernel<<<PREP_F4 / 256, 256>>>(W_O, k, v);
    attn_kernel<<<NQT * 32, 256, attn_smem>>>(q);
    proj_kernel<<<dim3(DM / 128, (B_SZ * S_CTX) / 128), 128, proj_smem>>>(b_O, out);
}